// round 1
// baseline (speedup 1.0000x reference)
#include <cuda_runtime.h>

// Shapes fixed by the problem: inputs [L,B,C,H,W] = [4,8,256,64,64] fp32, W [256,256] fp32.
#define L_DIM 4
#define B_DIM 8
#define C_DIM 256
#define HW_DIM 4096                    // 64*64, contiguous innermost plane
#define PLANES (L_DIM * B_DIM * C_DIM) // 8192

// Scratch (no device allocation allowed) — tiny.
__device__ float g_gap[PLANES];
__device__ float g_attn[PLANES];

// ---------------------------------------------------------------------------
// Kernel 1: global average pool over the HW plane.
// One block per (l,b,c) plane: 4096 contiguous floats = 1024 float4.
// 256 threads x 4 float4 each, fully coalesced streaming read.
// ---------------------------------------------------------------------------
__global__ __launch_bounds__(256) void gap_kernel(const float* __restrict__ in) {
    const int plane = blockIdx.x;
    const float4* __restrict__ p =
        reinterpret_cast<const float4*>(in) + (size_t)plane * (HW_DIM / 4);
    const int t = threadIdx.x;

    float s = 0.0f;
#pragma unroll
    for (int i = 0; i < 4; i++) {
        float4 v = p[t + i * 256];
        s += (v.x + v.y) + (v.z + v.w);
    }
    // warp reduce
#pragma unroll
    for (int o = 16; o > 0; o >>= 1) s += __shfl_xor_sync(0xFFFFFFFFu, s, o);

    __shared__ float ws[8];
    if ((t & 31) == 0) ws[t >> 5] = s;
    __syncthreads();
    if (t < 8) {
        float v = ws[t];
#pragma unroll
        for (int o = 4; o > 0; o >>= 1) v += __shfl_xor_sync(0xFFu, v, o);
        if (t == 0) g_gap[plane] = v * (1.0f / (float)HW_DIM);
    }
}

// ---------------------------------------------------------------------------
// Kernel 2: scores = gap @ W^T, softmax over L, all fused. Tiny (2.1 MFLOP).
// Grid: B_DIM blocks, C_DIM threads (thread d owns output channel d).
// ---------------------------------------------------------------------------
__global__ __launch_bounds__(C_DIM) void attn_kernel(const float* __restrict__ Wm) {
    const int b = blockIdx.x;
    const int d = threadIdx.x;

    __shared__ float gs[L_DIM][C_DIM];
#pragma unroll
    for (int l = 0; l < L_DIM; l++)
        gs[l][d] = g_gap[(l * B_DIM + b) * C_DIM + d];
    __syncthreads();

    const float* __restrict__ wrow = Wm + (size_t)d * C_DIM;
    float a0 = 0.f, a1 = 0.f, a2 = 0.f, a3 = 0.f;
#pragma unroll 8
    for (int c = 0; c < C_DIM; c++) {
        const float w = __ldg(&wrow[c]);
        a0 = fmaf(gs[0][c], w, a0);
        a1 = fmaf(gs[1][c], w, a1);
        a2 = fmaf(gs[2][c], w, a2);
        a3 = fmaf(gs[3][c], w, a3);
    }

    // softmax over the 4 layer scores
    const float m = fmaxf(fmaxf(a0, a1), fmaxf(a2, a3));
    const float e0 = __expf(a0 - m);
    const float e1 = __expf(a1 - m);
    const float e2 = __expf(a2 - m);
    const float e3 = __expf(a3 - m);
    const float inv = 1.0f / (e0 + e1 + e2 + e3);

    g_attn[(0 * B_DIM + b) * C_DIM + d] = e0 * inv;
    g_attn[(1 * B_DIM + b) * C_DIM + d] = e1 * inv;
    g_attn[(2 * B_DIM + b) * C_DIM + d] = e2 * inv;
    g_attn[(3 * B_DIM + b) * C_DIM + d] = e3 * inv;
}

// ---------------------------------------------------------------------------
// Kernel 3: out = inputs * attn[plane], float4 streaming.
// plane = idx4 >> 10 (1024 float4 per plane) -> warp-uniform attn load.
// ---------------------------------------------------------------------------
__global__ __launch_bounds__(256) void scale_kernel(const float4* __restrict__ in,
                                                    float4* __restrict__ out) {
    const int idx = blockIdx.x * blockDim.x + threadIdx.x;
    const float a = g_attn[idx >> 10];
    float4 v = in[idx];
    v.x *= a; v.y *= a; v.z *= a; v.w *= a;
    out[idx] = v;
}

extern "C" void kernel_launch(void* const* d_in, const int* in_sizes, int n_in,
                              void* d_out, int out_size) {
    (void)in_sizes; (void)n_in; (void)out_size;
    const float* in = (const float*)d_in[0];
    const float* Wm = (const float*)d_in[1];
    float* out = (float*)d_out;

    gap_kernel<<<PLANES, 256>>>(in);
    attn_kernel<<<B_DIM, C_DIM>>>(Wm);
    const int n4 = PLANES * (HW_DIM / 4);           // 8,388,608 float4
    scale_kernel<<<n4 / 256, 256>>>((const float4*)in, (float4*)out);
}

// round 5
// speedup vs baseline: 1.0789x; 1.0789x over previous
#include <cuda_runtime.h>

// Shapes fixed by the problem: inputs [L,B,C,H,W] = [4,8,256,64,64] fp32, W [256,256] fp32.
#define L_DIM 4
#define B_DIM 8
#define C_DIM 256
#define HW_DIM 4096                    // 64*64, contiguous innermost plane
#define PLANES (L_DIM * B_DIM * C_DIM) // 8192
#define N_FLOAT4 (PLANES * (HW_DIM / 4))   // 8,388,608 float4 total

// Scratch (no device allocation allowed) — tiny.
__device__ float g_gap[PLANES];
__device__ float g_attn[PLANES];

// ---------------------------------------------------------------------------
// Kernel 1: global average pool over the HW plane.
// One block per (l,b,c) plane: 4096 contiguous floats = 1024 float4.
// 256 threads x 4 float4 each, fully coalesced streaming read.
// Default cache policy so lines land in L2 for the scale pass to reuse.
// ---------------------------------------------------------------------------
__global__ __launch_bounds__(256) void gap_kernel(const float* __restrict__ in) {
    const int plane = blockIdx.x;
    const float4* __restrict__ p =
        reinterpret_cast<const float4*>(in) + (size_t)plane * (HW_DIM / 4);
    const int t = threadIdx.x;

    float4 v0 = p[t];
    float4 v1 = p[t + 256];
    float4 v2 = p[t + 512];
    float4 v3 = p[t + 768];
    float s = ((v0.x + v0.y) + (v0.z + v0.w)) + ((v1.x + v1.y) + (v1.z + v1.w))
            + ((v2.x + v2.y) + (v2.z + v2.w)) + ((v3.x + v3.y) + (v3.z + v3.w));

#pragma unroll
    for (int o = 16; o > 0; o >>= 1) s += __shfl_xor_sync(0xFFFFFFFFu, s, o);

    __shared__ float ws[8];
    if ((t & 31) == 0) ws[t >> 5] = s;
    __syncthreads();
    if (t < 8) {
        float v = ws[t];
#pragma unroll
        for (int o = 4; o > 0; o >>= 1) v += __shfl_xor_sync(0xFFu, v, o);
        if (t == 0) g_gap[plane] = v * (1.0f / (float)HW_DIM);
    }
}

// ---------------------------------------------------------------------------
// Kernel 2: scores = gap @ W^T, softmax over L, all fused. Tiny (2.1 MFLOP).
// Grid: B_DIM blocks, C_DIM threads (thread d owns output channel d).
// ---------------------------------------------------------------------------
__global__ __launch_bounds__(C_DIM) void attn_kernel(const float* __restrict__ Wm) {
    const int b = blockIdx.x;
    const int d = threadIdx.x;

    __shared__ float gs[L_DIM][C_DIM];
#pragma unroll
    for (int l = 0; l < L_DIM; l++)
        gs[l][d] = g_gap[(l * B_DIM + b) * C_DIM + d];
    __syncthreads();

    const float* __restrict__ wrow = Wm + (size_t)d * C_DIM;
    float a0 = 0.f, a1 = 0.f, a2 = 0.f, a3 = 0.f;
#pragma unroll 8
    for (int c = 0; c < C_DIM; c++) {
        const float w = __ldg(&wrow[c]);
        a0 = fmaf(gs[0][c], w, a0);
        a1 = fmaf(gs[1][c], w, a1);
        a2 = fmaf(gs[2][c], w, a2);
        a3 = fmaf(gs[3][c], w, a3);
    }

    const float m = fmaxf(fmaxf(a0, a1), fmaxf(a2, a3));
    const float e0 = __expf(a0 - m);
    const float e1 = __expf(a1 - m);
    const float e2 = __expf(a2 - m);
    const float e3 = __expf(a3 - m);
    const float inv = 1.0f / (e0 + e1 + e2 + e3);

    g_attn[(0 * B_DIM + b) * C_DIM + d] = e0 * inv;
    g_attn[(1 * B_DIM + b) * C_DIM + d] = e1 * inv;
    g_attn[(2 * B_DIM + b) * C_DIM + d] = e2 * inv;
    g_attn[(3 * B_DIM + b) * C_DIM + d] = e3 * inv;
}

// ---------------------------------------------------------------------------
// Kernel 3: out = inputs * attn[plane].
// - 8 float4 per thread, all loads front-batched (MLP_p1 = 8).
// - Blocks process chunks in REVERSE address order: gap_kernel just streamed
//   the input through L2 (126 MB), so the address-space TAIL is resident.
//   Reading tail-first converts a large fraction of the re-read into L2 hits.
// - Output stored with __stcs (evict-first) so the 128 MiB of writes don't
//   evict input lines the later (lower-address) blocks still need.
// Chunk = 2048 float4 (2 planes). Grid = 4096 blocks x 256 threads.
// ---------------------------------------------------------------------------
#define SCALE_V4_PER_THREAD 8
#define SCALE_CHUNK (256 * SCALE_V4_PER_THREAD)   // 2048 float4 per block

__global__ __launch_bounds__(256) void scale_kernel(const float4* __restrict__ in,
                                                    float4* __restrict__ out) {
    const int chunk = (int)gridDim.x - 1 - (int)blockIdx.x;   // reverse order
    const int base = chunk * SCALE_CHUNK + (int)threadIdx.x;

    float4 v[SCALE_V4_PER_THREAD];
#pragma unroll
    for (int k = 0; k < SCALE_V4_PER_THREAD; k++)
        v[k] = in[base + k * 256];

#pragma unroll
    for (int k = 0; k < SCALE_V4_PER_THREAD; k++) {
        const int idx = base + k * 256;
        const float a = g_attn[idx >> 10];        // warp-uniform (plane id)
        v[k].x *= a; v[k].y *= a; v[k].z *= a; v[k].w *= a;
        __stcs(&out[idx], v[k]);
    }
}

extern "C" void kernel_launch(void* const* d_in, const int* in_sizes, int n_in,
                              void* d_out, int out_size) {
    (void)in_sizes; (void)n_in; (void)out_size;
    const float* in = (const float*)d_in[0];
    const float* Wm = (const float*)d_in[1];
    float* out = (float*)d_out;

    gap_kernel<<<PLANES, 256>>>(in);
    attn_kernel<<<B_DIM, C_DIM>>>(Wm);
    scale_kernel<<<N_FLOAT4 / SCALE_CHUNK, 256>>>((const float4*)in, (float4*)out);
}

// round 7
// speedup vs baseline: 1.5289x; 1.4171x over previous
#include <cuda_runtime.h>

// Shapes fixed by the problem: inputs [L,B,C,H,W] = [4,8,256,64,64] fp32, W [256,256] fp32.
#define L_DIM 4
#define B_DIM 8
#define C_DIM 256
#define HW_DIM 4096                     // contiguous innermost plane
#define PLANES (L_DIM * B_DIM * C_DIM)  // 8192
#define NBLK 148                        // one block per SM; all resident -> grid barrier safe
#define NTHR 1024                       // 32 warps per block

// Scratch (no device allocation allowed) — tiny.
__device__ float g_gap[PLANES];
__device__ unsigned int g_bar = 0;      // grid-barrier arrival counter

// Trailing reset so every graph replay starts with g_bar == 0 (deterministic).
__global__ void reset_kernel() { g_bar = 0u; }

// ---------------------------------------------------------------------------
// Fused persistent kernel: GAP -> grid barrier -> (scores+softmax) -> scale.
// Block b owns contiguous planes [b*PLANES/NBLK, (b+1)*PLANES/NBLK): 55-56
// planes (~880 KB). Phase 3 re-reads exactly what phase 1 read on this SM,
// so the re-read hits L2 (126 MB vs 128 MiB total footprint).
// ---------------------------------------------------------------------------
__global__ __launch_bounds__(NTHR, 1) void fused_kernel(const float* __restrict__ in,
                                                        const float* __restrict__ Wm,
                                                        float* __restrict__ out) {
    const int bid  = blockIdx.x;
    const int wid  = threadIdx.x >> 5;    // 0..31
    const int lane = threadIdx.x & 31;
    const int pstart = (bid * PLANES) / NBLK;
    const int pend   = ((bid + 1) * PLANES) / NBLK;

    // ---------------- Phase 1: GAP (warp per plane) ----------------
    for (int p = pstart + wid; p < pend; p += 32) {
        const float4* __restrict__ pp =
            (const float4*)in + (size_t)p * (HW_DIM / 4);
        float s = 0.0f;
#pragma unroll
        for (int k = 0; k < 32; k += 8) {          // 4 batches of 8 loads (MLP=8)
            float4 v[8];
#pragma unroll
            for (int u = 0; u < 8; u++) v[u] = pp[lane + (k + u) * 32];
#pragma unroll
            for (int u = 0; u < 8; u++) s += (v[u].x + v[u].y) + (v[u].z + v[u].w);
        }
#pragma unroll
        for (int o = 16; o > 0; o >>= 1) s += __shfl_xor_sync(0xFFFFFFFFu, s, o);
        if (lane == 0) g_gap[p] = s * (1.0f / (float)HW_DIM);
    }

    // ---------------- Grid barrier (all 148 blocks resident) ----------------
    __threadfence();                       // release this thread's g_gap stores
    __syncthreads();
    if (threadIdx.x == 0) {
        atomicAdd(&g_bar, 1u);
        while (atomicAdd(&g_bar, 0u) < (unsigned)NBLK) __nanosleep(64);
        __threadfence();                   // acquire
    }
    __syncthreads();

    // ------------- Phase 2+3: per plane, softmax weight then scale -------------
    for (int p = pstart + wid; p < pend; p += 32) {
        const int c  = p & (C_DIM - 1);    // output channel d
        const int lb = p >> 8;             // l*B + b
        const int bb = lb & (B_DIM - 1);
        const int l  = lb >> 3;

        // scores s[l'] = dot(gap[l',bb,:], W[c,:]) — lanes split the 256-dim dot
        const float* __restrict__ wrow = Wm + (size_t)c * C_DIM;
        float a0 = 0.f, a1 = 0.f, a2 = 0.f, a3 = 0.f;
#pragma unroll
        for (int k = 0; k < 8; k++) {
            const int cc = lane + 32 * k;
            const float w = __ldg(&wrow[cc]);
            a0 = fmaf(__ldcg(&g_gap[(0 * B_DIM + bb) * C_DIM + cc]), w, a0);
            a1 = fmaf(__ldcg(&g_gap[(1 * B_DIM + bb) * C_DIM + cc]), w, a1);
            a2 = fmaf(__ldcg(&g_gap[(2 * B_DIM + bb) * C_DIM + cc]), w, a2);
            a3 = fmaf(__ldcg(&g_gap[(3 * B_DIM + bb) * C_DIM + cc]), w, a3);
        }
#pragma unroll
        for (int o = 16; o > 0; o >>= 1) {
            a0 += __shfl_xor_sync(0xFFFFFFFFu, a0, o);
            a1 += __shfl_xor_sync(0xFFFFFFFFu, a1, o);
            a2 += __shfl_xor_sync(0xFFFFFFFFu, a2, o);
            a3 += __shfl_xor_sync(0xFFFFFFFFu, a3, o);
        }
        const float m  = fmaxf(fmaxf(a0, a1), fmaxf(a2, a3));
        const float e0 = __expf(a0 - m);
        const float e1 = __expf(a1 - m);
        const float e2 = __expf(a2 - m);
        const float e3 = __expf(a3 - m);
        const float inv = 1.0f / (e0 + e1 + e2 + e3);
        const float el  = (l == 0) ? e0 : (l == 1) ? e1 : (l == 2) ? e2 : e3;
        const float a   = el * inv;

        // scale: reads should hit L2 (phase-1 residency); evict-first afterwards
        const float4* __restrict__ pp = (const float4*)in + (size_t)p * (HW_DIM / 4);
        float4* __restrict__ po       = (float4*)out + (size_t)p * (HW_DIM / 4);
#pragma unroll
        for (int k = 0; k < 32; k += 8) {
            float4 v[8];
#pragma unroll
            for (int u = 0; u < 8; u++) v[u] = __ldcs(&pp[lane + (k + u) * 32]);
#pragma unroll
            for (int u = 0; u < 8; u++) {
                v[u].x *= a; v[u].y *= a; v[u].z *= a; v[u].w *= a;
                __stcs(&po[lane + (k + u) * 32], v[u]);
            }
        }
    }
}

extern "C" void kernel_launch(void* const* d_in, const int* in_sizes, int n_in,
                              void* d_out, int out_size) {
    (void)in_sizes; (void)n_in; (void)out_size;
    const float* in = (const float*)d_in[0];
    const float* Wm = (const float*)d_in[1];
    float* out = (float*)d_out;

    fused_kernel<<<NBLK, NTHR>>>(in, Wm, out);
    reset_kernel<<<1, 1>>>();      // g_bar back to 0 for the next replay
}